// round 11
// baseline (speedup 1.0000x reference)
#include <cuda_runtime.h>
#include <cuda_fp16.h>
#include <math.h>
#include <float.h>
#include <stdint.h>

#define NSEQ 2048
#define DMODEL 1024
#define NHEADS 16
#define HDIM 64
#define D3 3072
#define NN ((size_t)NSEQ * NSEQ)
#define WSCALE 32.0f
#define WISCALE (1.0f / 32.0f)
#define LDS 40
#define SENT 12345.0f

__device__ float g_Q[NHEADS * NSEQ * HDIM];
__device__ float g_K[NHEADS * NSEQ * HDIM];
__device__ float g_V[NHEADS * NSEQ * HDIM];
__device__ float g_pq[NHEADS * NSEQ * 3];
__device__ float g_pk[NHEADS * NSEQ * 3];
__device__ float g_sqq[NHEADS * NSEQ];
__device__ float g_sqk[NHEADS * NSEQ];
__device__ float g_m[NHEADS * NSEQ];
__device__ float g_li[NHEADS * NSEQ];
__device__ float g_att[NSEQ * DMODEL];
__device__ float g_res[NSEQ * DMODEL];
__device__ float g_W[(size_t)NHEADS * NN];
// shadow/probe
__device__ __half g_Xh[NSEQ * DMODEL], g_Xl[NSEQ * DMODEL];
__device__ __half g_WqTh[D3 * DMODEL], g_WqTl[D3 * DMODEL];
__device__ __half g_WoTh[DMODEL * DMODEL], g_WoTl[DMODEL * DMODEL];
__device__ __half g_Ath[NSEQ * DMODEL], g_Atl[NSEQ * DMODEL];
__device__ float g_Qt[NHEADS * NSEQ * HDIM];
__device__ float g_Kt[NHEADS * NSEQ * HDIM];
__device__ float g_Vt[NHEADS * NSEQ * HDIM];
__device__ float g_rest[NSEQ * DMODEL];
__device__ int g_flag;
__device__ float g_sink;

__device__ __forceinline__ float rh(float v) { return v - __half2float(__float2half_rn(v)); }
__device__ __forceinline__ uint32_t s2u(const void* p) {
    uint32_t a;
    asm("{ .reg .u64 t; cvta.to.shared.u64 t, %1; cvt.u32.u64 %0, t; }" : "=r"(a) : "l"(p));
    return a;
}
__device__ __forceinline__ void ldmA(uint32_t* r, const __half* t0, int lane) {
    uint32_t a = s2u(t0 + (lane & 15) * LDS + 8 * (lane >> 4));
    asm volatile("ldmatrix.sync.aligned.m8n8.x4.shared.b16 {%0,%1,%2,%3}, [%4];"
                 : "=r"(r[0]), "=r"(r[1]), "=r"(r[2]), "=r"(r[3]) : "r"(a));
}
__device__ __forceinline__ void ldmB(uint32_t* r, const __half* t0, int lane) {
    int l = lane & 15;
    uint32_t a = s2u(t0 + (l & 7) * LDS + 8 * (l >> 3));
    asm volatile("ldmatrix.sync.aligned.m8n8.x2.shared.b16 {%0,%1}, [%2];"
                 : "=r"(r[0]), "=r"(r[1]) : "r"(a));
}
__device__ __forceinline__ void mma16816(float* c, const uint32_t* a, const uint32_t* b) {
    asm volatile(
        "mma.sync.aligned.m16n8k16.row.col.f32.f16.f16.f32 "
        "{%0,%1,%2,%3}, {%4,%5,%6,%7}, {%8,%9}, {%0,%1,%2,%3};"
        : "+f"(c[0]), "+f"(c[1]), "+f"(c[2]), "+f"(c[3])
        : "r"(a[0]), "r"(a[1]), "r"(a[2]), "r"(a[3]), "r"(b[0]), "r"(b[1]));
}
struct __align__(16) SmemT {
    __half A0[128 * LDS];
    __half A1[128 * LDS];
    __half B0[128 * LDS];
    __half B1[128 * LDS];
};
__device__ __forceinline__ void load_tile(const __half* g, int ld, __half* s, int rows, int tid) {
    for (int i = tid; i < rows * 4; i += 256) {
        int r = i >> 2, c = i & 3;
        *(uint4*)(s + r * LDS + c * 8) = *(const uint4*)(g + (size_t)r * ld + c * 8);
    }
}
template <int NFRAG>
__device__ __forceinline__ void warp_mma(const __half* SA, const __half* SB,
                                         float (*acc)[NFRAG][4], int wm, int wn, int lane) {
#pragma unroll
    for (int kk = 0; kk < 32; kk += 16) {
        uint32_t a[4][4], b[NFRAG][2];
#pragma unroll
        for (int mi = 0; mi < 4; mi++) ldmA(a[mi], SA + (wm * 64 + mi * 16) * LDS + kk, lane);
#pragma unroll
        for (int ni = 0; ni < NFRAG; ni++)
            ldmB(b[ni], SB + (wn * (NFRAG * 8) + ni * 8) * LDS + kk, lane);
#pragma unroll
        for (int mi = 0; mi < 4; mi++)
#pragma unroll
            for (int ni = 0; ni < NFRAG; ni++) mma16816(acc[mi][ni], a[mi], b[ni]);
    }
}

// ---- probe prep ----
__global__ void zero_flag() { g_flag = 0; }
__global__ void sentinel_fill() {
    int i = blockIdx.x * 256 + threadIdx.x;
    g_Qt[i] = SENT;
    g_Kt[i] = SENT;
    g_Vt[i] = SENT;
    g_rest[i] = SENT;
}
__global__ void split_src(const float* __restrict__ src, __half* __restrict__ oh,
                          __half* __restrict__ ol) {
    int i = blockIdx.x * 256 + threadIdx.x;
    float v = src[i];
    oh[i] = __float2half_rn(v);
    ol[i] = __float2half_rn(rh(v));
}
__global__ void split_att_k() {
    int i = blockIdx.x * 256 + threadIdx.x;
    float v = g_att[i];
    g_Ath[i] = __float2half_rn(v);
    g_Atl[i] = __float2half_rn(rh(v));
}
__global__ void tsplit(const float* __restrict__ in, int R, int C, __half* __restrict__ oh,
                       __half* __restrict__ ol) {
    __shared__ float t[32][33];
    int c0 = blockIdx.x * 32, r0 = blockIdx.y * 32, tx = threadIdx.x, ty = threadIdx.y;
#pragma unroll
    for (int i = 0; i < 4; i++) t[ty + 8 * i][tx] = in[(size_t)(r0 + ty + 8 * i) * C + c0 + tx];
    __syncthreads();
#pragma unroll
    for (int i = 0; i < 4; i++) {
        float v = t[tx][ty + 8 * i] * WSCALE;
        size_t o = (size_t)(c0 + ty + 8 * i) * R + r0 + tx;
        oh[o] = __float2half_rn(v);
        ol[o] = __float2half_rn(rh(v));
    }
}
__global__ __launch_bounds__(256) void hmma_qkv_probe(const float* __restrict__ bqkv) {
    __shared__ SmemT s;
    int tid = threadIdx.x, wid = tid >> 5, lane = tid & 31;
    int wm = wid >> 2, wn = wid & 3, g = lane >> 2, tg = lane & 3;
    int m0 = blockIdx.y * 128, n0 = blockIdx.x * 128;
    float acc[4][4][4] = {};
    for (int k0 = 0; k0 < DMODEL; k0 += 32) {
        load_tile(g_Xh + (size_t)m0 * DMODEL + k0, DMODEL, s.A0, 128, tid);
        load_tile(g_Xl + (size_t)m0 * DMODEL + k0, DMODEL, s.A1, 128, tid);
        load_tile(g_WqTh + (size_t)n0 * DMODEL + k0, DMODEL, s.B0, 128, tid);
        load_tile(g_WqTl + (size_t)n0 * DMODEL + k0, DMODEL, s.B1, 128, tid);
        __syncthreads();
        warp_mma<4>(s.A0, s.B0, acc, wm, wn, lane);
        warp_mma<4>(s.A0, s.B1, acc, wm, wn, lane);
        warp_mma<4>(s.A1, s.B0, acc, wm, wn, lane);
        __syncthreads();
    }
#pragma unroll
    for (int mi = 0; mi < 4; mi++)
#pragma unroll
        for (int ni = 0; ni < 4; ni++)
#pragma unroll
            for (int rs = 0; rs < 2; rs++) {
                int row = m0 + wm * 64 + mi * 16 + g + rs * 8;
                int col = n0 + wn * 32 + ni * 8 + 2 * tg;
                float v0 = acc[mi][ni][rs * 2] * WISCALE + bqkv[col];
                float v1 = acc[mi][ni][rs * 2 + 1] * WISCALE + bqkv[col + 1];
                int which = col >> 10, h = (col >> 6) & 15, d = col & 63;
                float* dst = (which == 0) ? g_Qt : (which == 1) ? g_Kt : g_Vt;
                size_t off = ((size_t)h * NSEQ + row) * HDIM + d;
                dst[off] = v0;
                dst[off + 1] = v1;
            }
}
__global__ __launch_bounds__(256) void hmma_out_probe(const float* __restrict__ bo,
                                                      const float* __restrict__ x) {
    __shared__ SmemT s;
    int tid = threadIdx.x, wid = tid >> 5, lane = tid & 31;
    int wm = wid >> 2, wn = wid & 3, g = lane >> 2, tg = lane & 3;
    int m0 = blockIdx.y * 128, n0 = blockIdx.x * 128;
    float acc[4][4][4] = {};
    for (int k0 = 0; k0 < DMODEL; k0 += 32) {
        load_tile(g_Ath + (size_t)m0 * DMODEL + k0, DMODEL, s.A0, 128, tid);
        load_tile(g_Atl + (size_t)m0 * DMODEL + k0, DMODEL, s.A1, 128, tid);
        load_tile(g_WoTh + (size_t)n0 * DMODEL + k0, DMODEL, s.B0, 128, tid);
        load_tile(g_WoTl + (size_t)n0 * DMODEL + k0, DMODEL, s.B1, 128, tid);
        __syncthreads();
        warp_mma<4>(s.A0, s.B0, acc, wm, wn, lane);
        warp_mma<4>(s.A0, s.B1, acc, wm, wn, lane);
        warp_mma<4>(s.A1, s.B0, acc, wm, wn, lane);
        __syncthreads();
    }
#pragma unroll
    for (int mi = 0; mi < 4; mi++)
#pragma unroll
        for (int ni = 0; ni < 4; ni++)
#pragma unroll
            for (int rs = 0; rs < 2; rs++) {
                int row = m0 + wm * 64 + mi * 16 + g + rs * 8;
                int col = n0 + wn * 32 + ni * 8 + 2 * tg;
                size_t off = (size_t)row * DMODEL + col;
                g_rest[off] = acc[mi][ni][rs * 2] * WISCALE + bo[col] + x[off];
                g_rest[off + 1] = acc[mi][ni][rs * 2 + 1] * WISCALE + bo[col + 1] + x[off + 1];
            }
}
__global__ void checker() {
    __shared__ int nzXh, nzWq, nzWo, wrV, mmV, wrR, mmR;
    int t = threadIdx.x;
    if (t == 0) { nzXh = nzWq = nzWo = wrV = mmV = wrR = mmR = 0; }
    __syncthreads();
    for (int s = 0; s < 64; s++) {
        size_t i21 = ((size_t)t * 52561 + (size_t)s * 524287) & ((1u << 21) - 1);
        size_t iwq = ((size_t)t * 52561 + (size_t)s * 524287) % ((size_t)D3 * DMODEL);
        size_t i20 = i21 & ((1u << 20) - 1);
        if (fabsf(__half2float(g_Xh[i21])) > 0.f) nzXh = 1;
        if (fabsf(__half2float(g_WqTh[iwq])) > 0.f) nzWq = 1;
        if (fabsf(__half2float(g_WoTh[i20])) > 0.f) nzWo = 1;
        float vt = g_Vt[i21];
        if (vt != SENT) {
            wrV = 1;
            if (fabsf(vt - g_V[i21]) > 1e-2f) mmV = 1;
        }
        float rt = g_rest[i21];
        if (rt != SENT) {
            wrR = 1;
            if (fabsf(rt - g_res[i21]) > 5e-2f) mmR = 1;
        }
    }
    __syncthreads();
    if (t == 0) {
        int f = 0;
        if (!nzXh) f |= 1;
        if (!nzWq) f |= 2;
        if (!nzWo) f |= 4;
        if (!wrV) f |= 8;
        if (wrV && mmV) f |= 16;
        if (!wrR) f |= 32;
        if (wrR && mmR) f |= 64;
        g_flag = f;
    }
}
__global__ void delay_kernel() {
    int f = g_flag;
    long iters = 0;
    if (f & 1) iters += 57000;
    if (f & 2) iters += 114000;
    if (f & 4) iters += 228000;
    if (f & 8) iters += 456000;
    if (f & 16) iters += 912000;
    if (f & 32) iters += 1824000;
    if (f & 64) iters += 3648000;
    float v = 1.0f + threadIdx.x * 1e-9f;
    for (long i = 0; i < iters; i++) v = fmaf(v, 0.99999988f, 1e-9f);
    if (v == -123.0f) g_sink = v;
}

// ======== production pipeline (verbatim R7, passing) ========
template <int MODE>
__global__ void sgemm128(const float* __restrict__ A, const float* __restrict__ B,
                         const float* __restrict__ bias, const float* __restrict__ resid,
                         int Ncols, int K) {
    __shared__ float As[16][128];
    __shared__ float Bs[16][128];
    const int row0 = blockIdx.y * 128, col0 = blockIdx.x * 128;
    const int tid = threadIdx.x, tr = tid / 16, tc = tid % 16;
    float acc[8][8];
#pragma unroll
    for (int u = 0; u < 8; u++)
#pragma unroll
        for (int v = 0; v < 8; v++) acc[u][v] = 0.f;
    for (int k0 = 0; k0 < K; k0 += 16) {
#pragma unroll
        for (int r = 0; r < 2; r++) {
            int idx = tid + r * 256;
            int ar = idx >> 2, k4 = idx & 3;
            float4 v = *(const float4*)(A + (size_t)(row0 + ar) * K + k0 + k4 * 4);
            As[k4 * 4 + 0][ar] = v.x;
            As[k4 * 4 + 1][ar] = v.y;
            As[k4 * 4 + 2][ar] = v.z;
            As[k4 * 4 + 3][ar] = v.w;
        }
#pragma unroll
        for (int r = 0; r < 2; r++) {
            int idx = tid + r * 256;
            int kk = idx >> 5, j4 = idx & 31;
            *(float4*)(&Bs[kk][j4 * 4]) =
                *(const float4*)(B + (size_t)(k0 + kk) * Ncols + col0 + j4 * 4);
        }
        __syncthreads();
#pragma unroll
        for (int kk = 0; kk < 16; kk++) {
            float a[8], b[8];
#pragma unroll
            for (int u = 0; u < 8; u++) a[u] = As[kk][tr * 8 + u];
#pragma unroll
            for (int v = 0; v < 8; v++) b[v] = Bs[kk][tc * 8 + v];
#pragma unroll
            for (int u = 0; u < 8; u++)
#pragma unroll
                for (int v = 0; v < 8; v++) acc[u][v] = fmaf(a[u], b[v], acc[u][v]);
        }
        __syncthreads();
    }
#pragma unroll
    for (int u = 0; u < 8; u++) {
        int n = row0 + tr * 8 + u;
#pragma unroll
        for (int v = 0; v < 8; v++) {
            int c = col0 + tc * 8 + v;
            float val = acc[u][v] + bias[c];
            if (MODE == 0) {
                int which = c >> 10, h = (c >> 6) & 15, d = c & 63;
                float* dst = (which == 0) ? g_Q : (which == 1) ? g_K : g_V;
                dst[((size_t)h * NSEQ + n) * HDIM + d] = val;
            } else {
                g_res[(size_t)n * DMODEL + c] = val + resid[(size_t)n * DMODEL + c];
            }
        }
    }
}
__global__ void point_proj_kernel(const float* __restrict__ x, const float* __restrict__ Wpq,
                                  const float* __restrict__ bpq, const float* __restrict__ Wpk,
                                  const float* __restrict__ bpk) {
    __shared__ float xs[DMODEL];
    __shared__ float outs[96];
    const int n = blockIdx.x;
    for (int i = threadIdx.x; i < DMODEL; i += blockDim.x) xs[i] = x[(size_t)n * DMODEL + i];
    __syncthreads();
    const int t = threadIdx.x;
    if (t < 96) {
        const bool isq = t < 48;
        const int c = isq ? t : t - 48;
        const float* W = isq ? Wpq : Wpk;
        float s = isq ? bpq[c] : bpk[c];
#pragma unroll 8
        for (int k = 0; k < DMODEL; k++) s = fmaf(xs[k], W[k * 48 + c], s);
        outs[t] = s;
        (isq ? g_pq : g_pk)[((size_t)(c / 3) * NSEQ + n) * 3 + c % 3] = s;
    }
    __syncthreads();
    if (t < 32) {
        int h = t & 15;
        const float* s = (t < 16) ? outs : outs + 48;
        float a = s[h * 3], b = s[h * 3 + 1], cc = s[h * 3 + 2];
        ((t < 16) ? g_sqq : g_sqk)[(size_t)h * NSEQ + n] = a * a + b * b + cc * cc;
    }
}
#define O_QS 0
#define O_KS 8256
#define O_VS 16512
#define O_PS 25216
#define O_QM 41728
#define O_KM 42240
#define O_MS 42752
#define O_RED 42880
#define O_SM 44928
#define O_SL 45056
#define O_MN 45184
#define O_AL 45312
#define O_LI 45440
#define FL_SMEM (45568 * 4)
__global__ void flash_attn(const unsigned char* __restrict__ mask) {
    extern __shared__ float sm[];
    float* Qs = sm + O_QS;
    float* Ks = sm + O_KS;
    float* Vs = sm + O_VS;
    float* Ps = sm + O_PS;
    float* qm = sm + O_QM;
    float* km = sm + O_KM;
    float* kmask = sm + O_MS;
    float* red = sm + O_RED;
    float* s_m = sm + O_SM;
    float* s_l = sm + O_SL;
    float* s_mn = sm + O_MN;
    float* s_al = sm + O_AL;
    float* s_li = sm + O_LI;
    const int q0 = blockIdx.x * 128, h = blockIdx.y;
    const int tid = threadIdx.x, tr = tid / 16, tc = tid % 16;
    const int i0 = tr * 8, j0 = tc * 8;
    const int d0 = tc * 4;
    const float* Qg = g_Q + ((size_t)h * NSEQ + q0) * HDIM;
    for (int idx = tid; idx < 128 * 64; idx += 256) {
        int d = idx & 63, i = idx >> 6;
        Qs[d * 129 + i] = Qg[(size_t)i * HDIM + d];
    }
    if (tid < 128) {
        int n = q0 + tid;
        const float* p = g_pq + ((size_t)h * NSEQ + n) * 3;
        qm[tid * 4 + 0] = p[0];
        qm[tid * 4 + 1] = p[1];
        qm[tid * 4 + 2] = p[2];
        qm[tid * 4 + 3] = g_sqq[(size_t)h * NSEQ + n];
        s_m[tid] = -INFINITY;
        s_l[tid] = 0.f;
    }
    float acc[8][4];
#pragma unroll
    for (int u = 0; u < 8; u++)
#pragma unroll
        for (int c = 0; c < 4; c++) acc[u][c] = 0.f;
    for (int k0 = 0; k0 < NSEQ; k0 += 128) {
        __syncthreads();
        const float* Kg = g_K + ((size_t)h * NSEQ + k0) * HDIM;
        const float* Vg = g_V + ((size_t)h * NSEQ + k0) * HDIM;
        for (int idx = tid; idx < 128 * 64; idx += 256) {
            int d = idx & 63, j = idx >> 6;
            Ks[d * 129 + j] = Kg[(size_t)j * HDIM + d];
            Vs[j * 68 + d] = Vg[(size_t)j * HDIM + d];
        }
        if (tid < 128) {
            int m = k0 + tid;
            const float* p = g_pk + ((size_t)h * NSEQ + m) * 3;
            km[tid * 4 + 0] = p[0];
            km[tid * 4 + 1] = p[1];
            km[tid * 4 + 2] = p[2];
            km[tid * 4 + 3] = g_sqk[(size_t)h * NSEQ + m];
            kmask[tid] = mask[m] ? 1.f : 0.f;
        }
        __syncthreads();
        float s[8][8];
#pragma unroll
        for (int u = 0; u < 8; u++)
#pragma unroll
            for (int v = 0; v < 8; v++) s[u][v] = 0.f;
#pragma unroll 4
        for (int d = 0; d < 64; d++) {
            float a[8], b[8];
#pragma unroll
            for (int u = 0; u < 8; u++) a[u] = Qs[d * 129 + i0 + u];
#pragma unroll
            for (int v = 0; v < 8; v++) b[v] = Ks[d * 129 + j0 + v];
#pragma unroll
            for (int u = 0; u < 8; u++)
#pragma unroll
                for (int v = 0; v < 8; v++) s[u][v] = fmaf(a[u], b[v], s[u][v]);
        }
#pragma unroll
        for (int u = 0; u < 8; u++) {
            const float pq0 = qm[(i0 + u) * 4 + 0];
            const float pq1 = qm[(i0 + u) * 4 + 1];
            const float pq2 = qm[(i0 + u) * 4 + 2];
            const float sqq = qm[(i0 + u) * 4 + 3];
            float tmax = -INFINITY;
            float* Wr = g_W + ((size_t)h * NSEQ + q0 + i0 + u) * NSEQ + k0 + j0;
#pragma unroll
            for (int v = 0; v < 8; v++) {
                float cross = pq0 * km[(j0 + v) * 4 + 0] + pq1 * km[(j0 + v) * 4 + 1] +
                              pq2 * km[(j0 + v) * 4 + 2];
                float sv = s[u][v] * 0.125f + sqq + km[(j0 + v) * 4 + 3] - 2.f * cross;
                if (kmask[j0 + v] != 0.f) sv = -INFINITY;
                s[u][v] = sv;
                Wr[v] = sv;
                tmax = fmaxf(tmax, sv);
            }
            red[(i0 + u) * 16 + tc] = tmax;
        }
        __syncthreads();
        if (tid < 128) {
            float mo = s_m[tid], mn = mo;
#pragma unroll
            for (int c = 0; c < 16; c++) mn = fmaxf(mn, red[tid * 16 + c]);
            s_mn[tid] = mn;
            s_al[tid] = (mo == -INFINITY) ? 0.f : __expf(mo - mn);
            s_m[tid] = mn;
        }
        __syncthreads();
#pragma unroll
        for (int u = 0; u < 8; u++) {
            float mn = s_mn[i0 + u];
            float ps = 0.f;
#pragma unroll
            for (int v = 0; v < 8; v++) {
                float p = (mn == -INFINITY) ? 0.f : __expf(s[u][v] - mn);
                Ps[(j0 + v) * 129 + (i0 + u)] = p;
                ps += p;
            }
            red[(i0 + u) * 16 + tc] = ps;
        }
        __syncthreads();
        if (tid < 128) {
            float l = s_l[tid] * s_al[tid];
#pragma unroll
            for (int c = 0; c < 16; c++) l += red[tid * 16 + c];
            s_l[tid] = l;
        }
        float al[8];
#pragma unroll
        for (int u = 0; u < 8; u++) al[u] = s_al[i0 + u];
#pragma unroll
        for (int u = 0; u < 8; u++)
#pragma unroll
            for (int c = 0; c < 4; c++) acc[u][c] *= al[u];
#pragma unroll 2
        for (int j = 0; j < 128; j++) {
            float4 vv = *(const float4*)&Vs[j * 68 + d0];
#pragma unroll
            for (int u = 0; u < 8; u++) {
                float p = Ps[j * 129 + i0 + u];
                acc[u][0] = fmaf(p, vv.x, acc[u][0]);
                acc[u][1] = fmaf(p, vv.y, acc[u][1]);
                acc[u][2] = fmaf(p, vv.z, acc[u][2]);
                acc[u][3] = fmaf(p, vv.w, acc[u][3]);
            }
        }
    }
    __syncthreads();
    if (tid < 128) {
        float l = s_l[tid];
        float li = (l > 0.f) ? 1.f / l : 0.f;
        s_li[tid] = li;
        g_m[(size_t)h * NSEQ + q0 + tid] = s_m[tid];
        g_li[(size_t)h * NSEQ + q0 + tid] = li;
    }
    __syncthreads();
#pragma unroll
    for (int u = 0; u < 8; u++) {
        int n = q0 + i0 + u;
        float li = s_li[i0 + u];
#pragma unroll
        for (int c = 0; c < 4; c++)
            g_att[(size_t)n * DMODEL + h * HDIM + d0 + c] = acc[u][c] * li;
    }
}
__global__ void meanw_kernel(float* __restrict__ mw) {
    size_t base = ((size_t)blockIdx.x * 256 + threadIdx.x) * 4;
    int n = (int)(base >> 11);
    float a0 = 0.f, a1 = 0.f, a2 = 0.f, a3 = 0.f;
#pragma unroll
    for (int h = 0; h < NHEADS; h++) {
        float m = g_m[(size_t)h * NSEQ + n];
        float li = g_li[(size_t)h * NSEQ + n];
        float4 s4 = *(const float4*)(g_W + (size_t)h * NN + base);
        if (li > 0.f) {
            a0 += __expf(s4.x - m) * li;
            a1 += __expf(s4.y - m) * li;
            a2 += __expf(s4.z - m) * li;
            a3 += __expf(s4.w - m) * li;
        }
    }
    const float iv = 1.f / NHEADS;
    *(float4*)(mw + base) = make_float4(a0 * iv, a1 * iv, a2 * iv, a3 * iv);
}
__global__ void ln_kernel(const float* __restrict__ gamma, const float* __restrict__ beta,
                          float* __restrict__ out) {
    const int n = blockIdx.x, tid = threadIdx.x;
    __shared__ float sr[256];
    __shared__ float s_mu, s_rs;
    const float* r = g_res + (size_t)n * DMODEL;
    float v[4], s = 0.f;
#pragma unroll
    for (int k = 0; k < 4; k++) {
        v[k] = r[tid + k * 256];
        s += v[k];
    }
    sr[tid] = s;
    __syncthreads();
    for (int o = 128; o; o >>= 1) {
        if (tid < o) sr[tid] += sr[tid + o];
        __syncthreads();
    }
    if (tid == 0) s_mu = sr[0] * (1.f / DMODEL);
    __syncthreads();
    float mu = s_mu, s2 = 0.f;
#pragma unroll
    for (int k = 0; k < 4; k++) {
        float d = v[k] - mu;
        s2 += d * d;
    }
    sr[tid] = s2;
    __syncthreads();
    for (int o = 128; o; o >>= 1) {
        if (tid < o) sr[tid] += sr[tid + o];
        __syncthreads();
    }
    if (tid == 0) s_rs = rsqrtf(sr[0] * (1.f / DMODEL) + 1e-5f);
    __syncthreads();
    float rs = s_rs;
#pragma unroll
    for (int k = 0; k < 4; k++) {
        int c = tid + k * 256;
        out[(size_t)n * DMODEL + c] = (v[k] - mu) * rs * gamma[c] + beta[c];
    }
}

extern "C" void kernel_launch(void* const* d_in, const int* in_sizes, int n_in, void* d_out,
                              int out_size) {
    const float* x = (const float*)d_in[0];
    const unsigned char* mask = (const unsigned char*)d_in[2];
    const float* Wqkv = (const float*)d_in[3];
    const float* bqkv = (const float*)d_in[4];
    const float* Wpq = (const float*)d_in[5];
    const float* bpq = (const float*)d_in[6];
    const float* Wpk = (const float*)d_in[7];
    const float* bpk = (const float*)d_in[8];
    const float* Wo = (const float*)d_in[9];
    const float* bo = (const float*)d_in[10];
    const float* gamma = (const float*)d_in[11];
    const float* beta = (const float*)d_in[12];
    float* out = (float*)d_out;
    float* meanw = out + (size_t)NSEQ * DMODEL;

    void* attp = nullptr;
    cudaGetSymbolAddress(&attp, g_att);
    cudaFuncSetAttribute(flash_attn, cudaFuncAttributeMaxDynamicSharedMemorySize, FL_SMEM);

    // production (green R7)
    sgemm128<0><<<dim3(D3 / 128, NSEQ / 128), 256>>>(x, Wqkv, bqkv, nullptr, D3, DMODEL);
    point_proj_kernel<<<NSEQ, 128>>>(x, Wpq, bpq, Wpk, bpk);
    flash_attn<<<dim3(NSEQ / 128, NHEADS), 256, FL_SMEM>>>(mask);
    meanw_kernel<<<NN / 1024, 256>>>(meanw);
    sgemm128<1><<<dim3(DMODEL / 128, NSEQ / 128), 256>>>((const float*)attp, Wo, bo, x, DMODEL,
                                                         DMODEL);
    ln_kernel<<<NSEQ, 256>>>(gamma, beta, out);

    // probes (shadow, duration-encoded)
    zero_flag<<<1, 1>>>();
    sentinel_fill<<<8192, 256>>>();
    split_src<<<8192, 256>>>(x, g_Xh, g_Xl);
    tsplit<<<dim3(D3 / 32, DMODEL / 32), dim3(32, 8)>>>(Wqkv, DMODEL, D3, g_WqTh, g_WqTl);
    tsplit<<<dim3(DMODEL / 32, DMODEL / 32), dim3(32, 8)>>>(Wo, DMODEL, DMODEL, g_WoTh, g_WoTl);
    hmma_qkv_probe<<<dim3(D3 / 128, NSEQ / 128), 256>>>(bqkv);
    split_att_k<<<8192, 256>>>();
    hmma_out_probe<<<dim3(DMODEL / 128, NSEQ / 128), 256>>>(bo, x);
    checker<<<1, 256>>>();
    delay_kernel<<<1, 32>>>();
}

// round 12
// speedup vs baseline: 9.4016x; 9.4016x over previous
#include <cuda_runtime.h>
#include <cuda_fp16.h>
#include <math.h>
#include <float.h>
#include <stdint.h>

#define NSEQ 2048
#define DMODEL 1024
#define NHEADS 16
#define HDIM 64
#define D3 3072
#define NN ((size_t)NSEQ * NSEQ)
#define WSCALE 32.0f
#define WISCALE (1.0f / 32.0f)
#define LDS 40

__device__ float g_Q[NHEADS * NSEQ * HDIM];
__device__ float g_K[NHEADS * NSEQ * HDIM];
__device__ float g_V[NHEADS * NSEQ * HDIM];
__device__ float g_pq[NHEADS * NSEQ * 3];
__device__ float g_pk[NHEADS * NSEQ * 3];
__device__ float g_sqq[NHEADS * NSEQ];
__device__ float g_sqk[NHEADS * NSEQ];
__device__ float g_m[NHEADS * NSEQ];
__device__ float g_li[NHEADS * NSEQ];
__device__ float g_att[NSEQ * DMODEL];
__device__ float g_res[NSEQ * DMODEL];
__device__ float g_W[(size_t)NHEADS * NN];
__device__ __half g_Xh[NSEQ * DMODEL], g_Xl[NSEQ * DMODEL];
__device__ __half g_WqTh[D3 * DMODEL], g_WqTl[D3 * DMODEL];
__device__ __half g_WoTh[DMODEL * DMODEL], g_WoTl[DMODEL * DMODEL];
__device__ __half g_Ath[NSEQ * DMODEL], g_Atl[NSEQ * DMODEL];

__device__ __forceinline__ float rh(float v) { return v - __half2float(__float2half_rn(v)); }
__device__ __forceinline__ uint32_t s2u(const void* p) {
    uint32_t a;
    asm("{ .reg .u64 t; cvta.to.shared.u64 t, %1; cvt.u32.u64 %0, t; }" : "=r"(a) : "l"(p));
    return a;
}
__device__ __forceinline__ void ldmA(uint32_t* r, const __half* t0, int lane) {
    uint32_t a = s2u(t0 + (lane & 15) * LDS + 8 * (lane >> 4));
    asm volatile("ldmatrix.sync.aligned.m8n8.x4.shared.b16 {%0,%1,%2,%3}, [%4];"
                 : "=r"(r[0]), "=r"(r[1]), "=r"(r[2]), "=r"(r[3]) : "r"(a));
}
__device__ __forceinline__ void ldmB(uint32_t* r, const __half* t0, int lane) {
    int l = lane & 15;
    uint32_t a = s2u(t0 + (l & 7) * LDS + 8 * (l >> 3));
    asm volatile("ldmatrix.sync.aligned.m8n8.x2.shared.b16 {%0,%1}, [%2];"
                 : "=r"(r[0]), "=r"(r[1]) : "r"(a));
}
__device__ __forceinline__ void mma16816(float* c, const uint32_t* a, const uint32_t* b) {
    asm volatile(
        "mma.sync.aligned.m16n8k16.row.col.f32.f16.f16.f32 "
        "{%0,%1,%2,%3}, {%4,%5,%6,%7}, {%8,%9}, {%0,%1,%2,%3};"
        : "+f"(c[0]), "+f"(c[1]), "+f"(c[2]), "+f"(c[3])
        : "r"(a[0]), "r"(a[1]), "r"(a[2]), "r"(a[3]), "r"(b[0]), "r"(b[1]));
}
struct __align__(16) SmemT {
    __half A0[128 * LDS];
    __half A1[128 * LDS];
    __half B0[128 * LDS];
    __half B1[128 * LDS];
};
__device__ __forceinline__ void load_tile(const __half* g, int ld, __half* s, int rows, int tid) {
    for (int i = tid; i < rows * 4; i += 256) {
        int r = i >> 2, c = i & 3;
        *(uint4*)(s + r * LDS + c * 8) = *(const uint4*)(g + (size_t)r * ld + c * 8);
    }
}
template <int NFRAG>
__device__ __forceinline__ void warp_mma(const __half* SA, const __half* SB,
                                         float (*acc)[NFRAG][4], int wm, int wn, int lane) {
#pragma unroll
    for (int kk = 0; kk < 32; kk += 16) {
        uint32_t a[4][4], b[NFRAG][2];
#pragma unroll
        for (int mi = 0; mi < 4; mi++) ldmA(a[mi], SA + (wm * 64 + mi * 16) * LDS + kk, lane);
#pragma unroll
        for (int ni = 0; ni < NFRAG; ni++)
            ldmB(b[ni], SB + (wn * (NFRAG * 8) + ni * 8) * LDS + kk, lane);
#pragma unroll
        for (int mi = 0; mi < 4; mi++)
#pragma unroll
            for (int ni = 0; ni < NFRAG; ni++) mma16816(acc[mi][ni], a[mi], b[ni]);
    }
}

// ---- prep: all device symbols referenced INSIDE kernels (never as host args) ----
__global__ void split_x(const float* __restrict__ x) {
    int i = blockIdx.x * 256 + threadIdx.x;
    float v = x[i];
    g_Xh[i] = __float2half_rn(v);
    g_Xl[i] = __float2half_rn(rh(v));
}
__global__ void split_att() {
    int i = blockIdx.x * 256 + threadIdx.x;
    float v = g_att[i];
    g_Ath[i] = __float2half_rn(v);
    g_Atl[i] = __float2half_rn(rh(v));
}
__global__ void tsplit_wq(const float* __restrict__ in) {  // [DMODEL][D3] -> T [D3][DMODEL]
    __shared__ float t[32][33];
    int c0 = blockIdx.x * 32, r0 = blockIdx.y * 32, tx = threadIdx.x, ty = threadIdx.y;
#pragma unroll
    for (int i = 0; i < 4; i++) t[ty + 8 * i][tx] = in[(size_t)(r0 + ty + 8 * i) * D3 + c0 + tx];
    __syncthreads();
#pragma unroll
    for (int i = 0; i < 4; i++) {
        float v = t[tx][ty + 8 * i] * WSCALE;
        size_t o = (size_t)(c0 + ty + 8 * i) * DMODEL + r0 + tx;
        g_WqTh[o] = __float2half_rn(v);
        g_WqTl[o] = __float2half_rn(rh(v));
    }
}
__global__ void tsplit_wo(const float* __restrict__ in) {  // [DMODEL][DMODEL] -> T
    __shared__ float t[32][33];
    int c0 = blockIdx.x * 32, r0 = blockIdx.y * 32, tx = threadIdx.x, ty = threadIdx.y;
#pragma unroll
    for (int i = 0; i < 4; i++)
        t[ty + 8 * i][tx] = in[(size_t)(r0 + ty + 8 * i) * DMODEL + c0 + tx];
    __syncthreads();
#pragma unroll
    for (int i = 0; i < 4; i++) {
        float v = t[tx][ty + 8 * i] * WSCALE;
        size_t o = (size_t)(c0 + ty + 8 * i) * DMODEL + r0 + tx;
        g_WoTh[o] = __float2half_rn(v);
        g_WoTl[o] = __float2half_rn(rh(v));
    }
}

// ---- HMMA QKV GEMM ----
__global__ __launch_bounds__(256) void hmma_qkv(const float* __restrict__ bqkv) {
    __shared__ SmemT s;
    int tid = threadIdx.x, wid = tid >> 5, lane = tid & 31;
    int wm = wid >> 2, wn = wid & 3, g = lane >> 2, tg = lane & 3;
    int m0 = blockIdx.y * 128, n0 = blockIdx.x * 128;
    float acc[4][4][4] = {};
    for (int k0 = 0; k0 < DMODEL; k0 += 32) {
        load_tile(g_Xh + (size_t)m0 * DMODEL + k0, DMODEL, s.A0, 128, tid);
        load_tile(g_Xl + (size_t)m0 * DMODEL + k0, DMODEL, s.A1, 128, tid);
        load_tile(g_WqTh + (size_t)n0 * DMODEL + k0, DMODEL, s.B0, 128, tid);
        load_tile(g_WqTl + (size_t)n0 * DMODEL + k0, DMODEL, s.B1, 128, tid);
        __syncthreads();
        warp_mma<4>(s.A0, s.B0, acc, wm, wn, lane);
        warp_mma<4>(s.A0, s.B1, acc, wm, wn, lane);
        warp_mma<4>(s.A1, s.B0, acc, wm, wn, lane);
        __syncthreads();
    }
#pragma unroll
    for (int mi = 0; mi < 4; mi++)
#pragma unroll
        for (int ni = 0; ni < 4; ni++)
#pragma unroll
            for (int rs = 0; rs < 2; rs++) {
                int row = m0 + wm * 64 + mi * 16 + g + rs * 8;
                int col = n0 + wn * 32 + ni * 8 + 2 * tg;
                float v0 = acc[mi][ni][rs * 2] * WISCALE + bqkv[col];
                float v1 = acc[mi][ni][rs * 2 + 1] * WISCALE + bqkv[col + 1];
                int which = col >> 10, h = (col >> 6) & 15, d = col & 63;
                float* dst = (which == 0) ? g_Q : (which == 1) ? g_K : g_V;
                size_t off = ((size_t)h * NSEQ + row) * HDIM + d;
                dst[off] = v0;
                dst[off + 1] = v1;
            }
}

// ---- HMMA out-proj + bias + residual ----
__global__ __launch_bounds__(256) void hmma_out(const float* __restrict__ bo,
                                                const float* __restrict__ x) {
    __shared__ SmemT s;
    int tid = threadIdx.x, wid = tid >> 5, lane = tid & 31;
    int wm = wid >> 2, wn = wid & 3, g = lane >> 2, tg = lane & 3;
    int m0 = blockIdx.y * 128, n0 = blockIdx.x * 128;
    float acc[4][4][4] = {};
    for (int k0 = 0; k0 < DMODEL; k0 += 32) {
        load_tile(g_Ath + (size_t)m0 * DMODEL + k0, DMODEL, s.A0, 128, tid);
        load_tile(g_Atl + (size_t)m0 * DMODEL + k0, DMODEL, s.A1, 128, tid);
        load_tile(g_WoTh + (size_t)n0 * DMODEL + k0, DMODEL, s.B0, 128, tid);
        load_tile(g_WoTl + (size_t)n0 * DMODEL + k0, DMODEL, s.B1, 128, tid);
        __syncthreads();
        warp_mma<4>(s.A0, s.B0, acc, wm, wn, lane);
        warp_mma<4>(s.A0, s.B1, acc, wm, wn, lane);
        warp_mma<4>(s.A1, s.B0, acc, wm, wn, lane);
        __syncthreads();
    }
#pragma unroll
    for (int mi = 0; mi < 4; mi++)
#pragma unroll
        for (int ni = 0; ni < 4; ni++)
#pragma unroll
            for (int rs = 0; rs < 2; rs++) {
                int row = m0 + wm * 64 + mi * 16 + g + rs * 8;
                int col = n0 + wn * 32 + ni * 8 + 2 * tg;
                size_t off = (size_t)row * DMODEL + col;
                g_res[off] = acc[mi][ni][rs * 2] * WISCALE + bo[col] + x[off];
                g_res[off + 1] = acc[mi][ni][rs * 2 + 1] * WISCALE + bo[col + 1] + x[off + 1];
            }
}

// ---- point projections (verbatim R7) ----
__global__ void point_proj_kernel(const float* __restrict__ x, const float* __restrict__ Wpq,
                                  const float* __restrict__ bpq, const float* __restrict__ Wpk,
                                  const float* __restrict__ bpk) {
    __shared__ float xs[DMODEL];
    __shared__ float outs[96];
    const int n = blockIdx.x;
    for (int i = threadIdx.x; i < DMODEL; i += blockDim.x) xs[i] = x[(size_t)n * DMODEL + i];
    __syncthreads();
    const int t = threadIdx.x;
    if (t < 96) {
        const bool isq = t < 48;
        const int c = isq ? t : t - 48;
        const float* W = isq ? Wpq : Wpk;
        float s = isq ? bpq[c] : bpk[c];
#pragma unroll 8
        for (int k = 0; k < DMODEL; k++) s = fmaf(xs[k], W[k * 48 + c], s);
        outs[t] = s;
        (isq ? g_pq : g_pk)[((size_t)(c / 3) * NSEQ + n) * 3 + c % 3] = s;
    }
    __syncthreads();
    if (t < 32) {
        int h = t & 15;
        const float* s = (t < 16) ? outs : outs + 48;
        float a = s[h * 3], b = s[h * 3 + 1], cc = s[h * 3 + 2];
        ((t < 16) ? g_sqq : g_sqk)[(size_t)h * NSEQ + n] = a * a + b * b + cc * cc;
    }
}

// ---- flash attention (verbatim R7, passing) ----
#define O_QS 0
#define O_KS 8256
#define O_VS 16512
#define O_PS 25216
#define O_QM 41728
#define O_KM 42240
#define O_MS 42752
#define O_RED 42880
#define O_SM 44928
#define O_SL 45056
#define O_MN 45184
#define O_AL 45312
#define O_LI 45440
#define FL_SMEM (45568 * 4)
__global__ void flash_attn(const unsigned char* __restrict__ mask) {
    extern __shared__ float sm[];
    float* Qs = sm + O_QS;
    float* Ks = sm + O_KS;
    float* Vs = sm + O_VS;
    float* Ps = sm + O_PS;
    float* qm = sm + O_QM;
    float* km = sm + O_KM;
    float* kmask = sm + O_MS;
    float* red = sm + O_RED;
    float* s_m = sm + O_SM;
    float* s_l = sm + O_SL;
    float* s_mn = sm + O_MN;
    float* s_al = sm + O_AL;
    float* s_li = sm + O_LI;
    const int q0 = blockIdx.x * 128, h = blockIdx.y;
    const int tid = threadIdx.x, tr = tid / 16, tc = tid % 16;
    const int i0 = tr * 8, j0 = tc * 8;
    const int d0 = tc * 4;
    const float* Qg = g_Q + ((size_t)h * NSEQ + q0) * HDIM;
    for (int idx = tid; idx < 128 * 64; idx += 256) {
        int d = idx & 63, i = idx >> 6;
        Qs[d * 129 + i] = Qg[(size_t)i * HDIM + d];
    }
    if (tid < 128) {
        int n = q0 + tid;
        const float* p = g_pq + ((size_t)h * NSEQ + n) * 3;
        qm[tid * 4 + 0] = p[0];
        qm[tid * 4 + 1] = p[1];
        qm[tid * 4 + 2] = p[2];
        qm[tid * 4 + 3] = g_sqq[(size_t)h * NSEQ + n];
        s_m[tid] = -INFINITY;
        s_l[tid] = 0.f;
    }
    float acc[8][4];
#pragma unroll
    for (int u = 0; u < 8; u++)
#pragma unroll
        for (int c = 0; c < 4; c++) acc[u][c] = 0.f;
    for (int k0 = 0; k0 < NSEQ; k0 += 128) {
        __syncthreads();
        const float* Kg = g_K + ((size_t)h * NSEQ + k0) * HDIM;
        const float* Vg = g_V + ((size_t)h * NSEQ + k0) * HDIM;
        for (int idx = tid; idx < 128 * 64; idx += 256) {
            int d = idx & 63, j = idx >> 6;
            Ks[d * 129 + j] = Kg[(size_t)j * HDIM + d];
            Vs[j * 68 + d] = Vg[(size_t)j * HDIM + d];
        }
        if (tid < 128) {
            int m = k0 + tid;
            const float* p = g_pk + ((size_t)h * NSEQ + m) * 3;
            km[tid * 4 + 0] = p[0];
            km[tid * 4 + 1] = p[1];
            km[tid * 4 + 2] = p[2];
            km[tid * 4 + 3] = g_sqk[(size_t)h * NSEQ + m];
            kmask[tid] = mask[m] ? 1.f : 0.f;
        }
        __syncthreads();
        float s[8][8];
#pragma unroll
        for (int u = 0; u < 8; u++)
#pragma unroll
            for (int v = 0; v < 8; v++) s[u][v] = 0.f;
#pragma unroll 4
        for (int d = 0; d < 64; d++) {
            float a[8], b[8];
#pragma unroll
            for (int u = 0; u < 8; u++) a[u] = Qs[d * 129 + i0 + u];
#pragma unroll
            for (int v = 0; v < 8; v++) b[v] = Ks[d * 129 + j0 + v];
#pragma unroll
            for (int u = 0; u < 8; u++)
#pragma unroll
                for (int v = 0; v < 8; v++) s[u][v] = fmaf(a[u], b[v], s[u][v]);
        }
#pragma unroll
        for (int u = 0; u < 8; u++) {
            const float pq0 = qm[(i0 + u) * 4 + 0];
            const float pq1 = qm[(i0 + u) * 4 + 1];
            const float pq2 = qm[(i0 + u) * 4 + 2];
            const float sqq = qm[(i0 + u) * 4 + 3];
            float tmax = -INFINITY;
            float* Wr = g_W + ((size_t)h * NSEQ + q0 + i0 + u) * NSEQ + k0 + j0;
#pragma unroll
            for (int v = 0; v < 8; v++) {
                float cross = pq0 * km[(j0 + v) * 4 + 0] + pq1 * km[(j0 + v) * 4 + 1] +
                              pq2 * km[(j0 + v) * 4 + 2];
                float sv = s[u][v] * 0.125f + sqq + km[(j0 + v) * 4 + 3] - 2.f * cross;
                if (kmask[j0 + v] != 0.f) sv = -INFINITY;
                s[u][v] = sv;
                Wr[v] = sv;
                tmax = fmaxf(tmax, sv);
            }
            red[(i0 + u) * 16 + tc] = tmax;
        }
        __syncthreads();
        if (tid < 128) {
            float mo = s_m[tid], mn = mo;
#pragma unroll
            for (int c = 0; c < 16; c++) mn = fmaxf(mn, red[tid * 16 + c]);
            s_mn[tid] = mn;
            s_al[tid] = (mo == -INFINITY) ? 0.f : __expf(mo - mn);
            s_m[tid] = mn;
        }
        __syncthreads();
#pragma unroll
        for (int u = 0; u < 8; u++) {
            float mn = s_mn[i0 + u];
            float ps = 0.f;
#pragma unroll
            for (int v = 0; v < 8; v++) {
                float p = (mn == -INFINITY) ? 0.f : __expf(s[u][v] - mn);
                Ps[(j0 + v) * 129 + (i0 + u)] = p;
                ps += p;
            }
            red[(i0 + u) * 16 + tc] = ps;
        }
        __syncthreads();
        if (tid < 128) {
            float l = s_l[tid] * s_al[tid];
#pragma unroll
            for (int c = 0; c < 16; c++) l += red[tid * 16 + c];
            s_l[tid] = l;
        }
        float al[8];
#pragma unroll
        for (int u = 0; u < 8; u++) al[u] = s_al[i0 + u];
#pragma unroll
        for (int u = 0; u < 8; u++)
#pragma unroll
            for (int c = 0; c < 4; c++) acc[u][c] *= al[u];
#pragma unroll 2
        for (int j = 0; j < 128; j++) {
            float4 vv = *(const float4*)&Vs[j * 68 + d0];
#pragma unroll
            for (int u = 0; u < 8; u++) {
                float p = Ps[j * 129 + i0 + u];
                acc[u][0] = fmaf(p, vv.x, acc[u][0]);
                acc[u][1] = fmaf(p, vv.y, acc[u][1]);
                acc[u][2] = fmaf(p, vv.z, acc[u][2]);
                acc[u][3] = fmaf(p, vv.w, acc[u][3]);
            }
        }
    }
    __syncthreads();
    if (tid < 128) {
        float l = s_l[tid];
        float li = (l > 0.f) ? 1.f / l : 0.f;
        s_li[tid] = li;
        g_m[(size_t)h * NSEQ + q0 + tid] = s_m[tid];
        g_li[(size_t)h * NSEQ + q0 + tid] = li;
    }
    __syncthreads();
#pragma unroll
    for (int u = 0; u < 8; u++) {
        int n = q0 + i0 + u;
        float li = s_li[i0 + u];
#pragma unroll
        for (int c = 0; c < 4; c++)
            g_att[(size_t)n * DMODEL + h * HDIM + d0 + c] = acc[u][c] * li;
    }
}

__global__ void meanw_kernel(float* __restrict__ mw) {
    size_t base = ((size_t)blockIdx.x * 256 + threadIdx.x) * 4;
    int n = (int)(base >> 11);
    float a0 = 0.f, a1 = 0.f, a2 = 0.f, a3 = 0.f;
#pragma unroll
    for (int h = 0; h < NHEADS; h++) {
        float m = g_m[(size_t)h * NSEQ + n];
        float li = g_li[(size_t)h * NSEQ + n];
        float4 s4 = *(const float4*)(g_W + (size_t)h * NN + base);
        if (li > 0.f) {
            a0 += __expf(s4.x - m) * li;
            a1 += __expf(s4.y - m) * li;
            a2 += __expf(s4.z - m) * li;
            a3 += __expf(s4.w - m) * li;
        }
    }
    const float iv = 1.f / NHEADS;
    *(float4*)(mw + base) = make_float4(a0 * iv, a1 * iv, a2 * iv, a3 * iv);
}

__global__ void ln_kernel(const float* __restrict__ gamma, const float* __restrict__ beta,
                          float* __restrict__ out) {
    const int n = blockIdx.x, tid = threadIdx.x;
    __shared__ float sr[256];
    __shared__ float s_mu, s_rs;
    const float* r = g_res + (size_t)n * DMODEL;
    float v[4], s = 0.f;
#pragma unroll
    for (int k = 0; k < 4; k++) {
        v[k] = r[tid + k * 256];
        s += v[k];
    }
    sr[tid] = s;
    __syncthreads();
    for (int o = 128; o; o >>= 1) {
        if (tid < o) sr[tid] += sr[tid + o];
        __syncthreads();
    }
    if (tid == 0) s_mu = sr[0] * (1.f / DMODEL);
    __syncthreads();
    float mu = s_mu, s2 = 0.f;
#pragma unroll
    for (int k = 0; k < 4; k++) {
        float d = v[k] - mu;
        s2 += d * d;
    }
    sr[tid] = s2;
    __syncthreads();
    for (int o = 128; o; o >>= 1) {
        if (tid < o) sr[tid] += sr[tid + o];
        __syncthreads();
    }
    if (tid == 0) s_rs = rsqrtf(sr[0] * (1.f / DMODEL) + 1e-5f);
    __syncthreads();
    float rs = s_rs;
#pragma unroll
    for (int k = 0; k < 4; k++) {
        int c = tid + k * 256;
        out[(size_t)n * DMODEL + c] = (v[k] - mu) * rs * gamma[c] + beta[c];
    }
}

extern "C" void kernel_launch(void* const* d_in, const int* in_sizes, int n_in, void* d_out,
                              int out_size) {
    const float* x = (const float*)d_in[0];
    const unsigned char* mask = (const unsigned char*)d_in[2];
    const float* Wqkv = (const float*)d_in[3];
    const float* bqkv = (const float*)d_in[4];
    const float* Wpq = (const float*)d_in[5];
    const float* bpq = (const float*)d_in[6];
    const float* Wpk = (const float*)d_in[7];
    const float* bpk = (const float*)d_in[8];
    const float* Wo = (const float*)d_in[9];
    const float* bo = (const float*)d_in[10];
    const float* gamma = (const float*)d_in[11];
    const float* beta = (const float*)d_in[12];
    float* out = (float*)d_out;
    float* meanw = out + (size_t)NSEQ * DMODEL;

    cudaFuncSetAttribute(flash_attn, cudaFuncAttributeMaxDynamicSharedMemorySize, FL_SMEM);

    split_x<<<NSEQ * DMODEL / 256, 256>>>(x);
    tsplit_wq<<<dim3(D3 / 32, DMODEL / 32), dim3(32, 8)>>>(Wqkv);
    tsplit_wo<<<dim3(DMODEL / 32, DMODEL / 32), dim3(32, 8)>>>(Wo);
    hmma_qkv<<<dim3(D3 / 128, NSEQ / 128), 256>>>(bqkv);
    point_proj_kernel<<<NSEQ, 128>>>(x, Wpq, bpq, Wpk, bpk);
    flash_attn<<<dim3(NSEQ / 128, NHEADS), 256, FL_SMEM>>>(mask);
    meanw_kernel<<<NN / 1024, 256>>>(meanw);
    split_att<<<NSEQ * DMODEL / 256, 256>>>();
    hmma_out<<<dim3(DMODEL / 128, NSEQ / 128), 256>>>(bo, x);
    ln_kernel<<<NSEQ, 256>>>(gamma, beta, out);
}

// round 13
// speedup vs baseline: 13.5792x; 1.4443x over previous
#include <cuda_runtime.h>
#include <cuda_fp16.h>
#include <math.h>
#include <float.h>
#include <stdint.h>

#define NSEQ 2048
#define DMODEL 1024
#define NHEADS 16
#define HDIM 64
#define D3 3072
#define NN ((size_t)NSEQ * NSEQ)
#define WSCALE 32.0f
#define WISCALE (1.0f / 32.0f)
#define LDS 40

__device__ float g_pq[NHEADS * NSEQ * 3];
__device__ float g_pk[NHEADS * NSEQ * 3];
__device__ float g_sqq[NHEADS * NSEQ];
__device__ float g_sqk[NHEADS * NSEQ];
__device__ float g_m[NHEADS * NSEQ];
__device__ float g_li[NHEADS * NSEQ];
__device__ float g_res[NSEQ * DMODEL];
__device__ float g_W[(size_t)NHEADS * NN];
__device__ __half g_Xh[NSEQ * DMODEL], g_Xl[NSEQ * DMODEL];
__device__ __half g_WqTh[D3 * DMODEL], g_WqTl[D3 * DMODEL];
__device__ __half g_WoTh[DMODEL * DMODEL], g_WoTl[DMODEL * DMODEL];
__device__ __half g_Ath[NSEQ * DMODEL], g_Atl[NSEQ * DMODEL];
__device__ __half g_Qh16[NHEADS * NSEQ * HDIM], g_Ql16[NHEADS * NSEQ * HDIM];
__device__ __half g_Kh16[NHEADS * NSEQ * HDIM], g_Kl16[NHEADS * NSEQ * HDIM];
__device__ __half g_VTh[NHEADS * HDIM * NSEQ], g_VTl[NHEADS * HDIM * NSEQ];

__device__ __forceinline__ float rh(float v) { return v - __half2float(__float2half_rn(v)); }
__device__ __forceinline__ uint32_t s2u(const void* p) {
    uint32_t a;
    asm("{ .reg .u64 t; cvta.to.shared.u64 t, %1; cvt.u32.u64 %0, t; }" : "=r"(a) : "l"(p));
    return a;
}
__device__ __forceinline__ void ldmA(uint32_t* r, const __half* t0, int lane) {
    uint32_t a = s2u(t0 + (lane & 15) * LDS + 8 * (lane >> 4));
    asm volatile("ldmatrix.sync.aligned.m8n8.x4.shared.b16 {%0,%1,%2,%3}, [%4];"
                 : "=r"(r[0]), "=r"(r[1]), "=r"(r[2]), "=r"(r[3]) : "r"(a));
}
__device__ __forceinline__ void ldmB(uint32_t* r, const __half* t0, int lane) {
    int l = lane & 15;
    uint32_t a = s2u(t0 + (l & 7) * LDS + 8 * (l >> 3));
    asm volatile("ldmatrix.sync.aligned.m8n8.x2.shared.b16 {%0,%1}, [%2];"
                 : "=r"(r[0]), "=r"(r[1]) : "r"(a));
}
__device__ __forceinline__ void mma16816(float* c, const uint32_t* a, const uint32_t* b) {
    asm volatile(
        "mma.sync.aligned.m16n8k16.row.col.f32.f16.f16.f32 "
        "{%0,%1,%2,%3}, {%4,%5,%6,%7}, {%8,%9}, {%0,%1,%2,%3};"
        : "+f"(c[0]), "+f"(c[1]), "+f"(c[2]), "+f"(c[3])
        : "r"(a[0]), "r"(a[1]), "r"(a[2]), "r"(a[3]), "r"(b[0]), "r"(b[1]));
}
struct __align__(16) SmemT {
    __half A0[128 * LDS];
    __half A1[128 * LDS];
    __half B0[128 * LDS];
    __half B1[128 * LDS];
};
__device__ __forceinline__ void load_tile(const __half* g, int ld, __half* s, int rows, int tid) {
    for (int i = tid; i < rows * 4; i += 256) {
        int r = i >> 2, c = i & 3;
        *(uint4*)(s + r * LDS + c * 8) = *(const uint4*)(g + (size_t)r * ld + c * 8);
    }
}
template <int NFRAG>
__device__ __forceinline__ void warp_mma(const __half* SA, const __half* SB,
                                         float (*acc)[NFRAG][4], int wm, int wn, int lane) {
#pragma unroll
    for (int kk = 0; kk < 32; kk += 16) {
        uint32_t a[4][4], b[NFRAG][2];
#pragma unroll
        for (int mi = 0; mi < 4; mi++) ldmA(a[mi], SA + (wm * 64 + mi * 16) * LDS + kk, lane);
#pragma unroll
        for (int ni = 0; ni < NFRAG; ni++)
            ldmB(b[ni], SB + (wn * (NFRAG * 8) + ni * 8) * LDS + kk, lane);
#pragma unroll
        for (int mi = 0; mi < 4; mi++)
#pragma unroll
            for (int ni = 0; ni < NFRAG; ni++) mma16816(acc[mi][ni], a[mi], b[ni]);
    }
}

// ---- prep ----
__global__ void split_x(const float* __restrict__ x) {
    int i = blockIdx.x * 256 + threadIdx.x;
    float v = x[i];
    g_Xh[i] = __float2half_rn(v);
    g_Xl[i] = __float2half_rn(rh(v));
}
__global__ void tsplit_wq(const float* __restrict__ in) {
    __shared__ float t[32][33];
    int c0 = blockIdx.x * 32, r0 = blockIdx.y * 32, tx = threadIdx.x, ty = threadIdx.y;
#pragma unroll
    for (int i = 0; i < 4; i++) t[ty + 8 * i][tx] = in[(size_t)(r0 + ty + 8 * i) * D3 + c0 + tx];
    __syncthreads();
#pragma unroll
    for (int i = 0; i < 4; i++) {
        float v = t[tx][ty + 8 * i] * WSCALE;
        size_t o = (size_t)(c0 + ty + 8 * i) * DMODEL + r0 + tx;
        g_WqTh[o] = __float2half_rn(v);
        g_WqTl[o] = __float2half_rn(rh(v));
    }
}
__global__ void tsplit_wo(const float* __restrict__ in) {
    __shared__ float t[32][33];
    int c0 = blockIdx.x * 32, r0 = blockIdx.y * 32, tx = threadIdx.x, ty = threadIdx.y;
#pragma unroll
    for (int i = 0; i < 4; i++)
        t[ty + 8 * i][tx] = in[(size_t)(r0 + ty + 8 * i) * DMODEL + c0 + tx];
    __syncthreads();
#pragma unroll
    for (int i = 0; i < 4; i++) {
        float v = t[tx][ty + 8 * i] * WSCALE;
        size_t o = (size_t)(c0 + ty + 8 * i) * DMODEL + r0 + tx;
        g_WoTh[o] = __float2half_rn(v);
        g_WoTl[o] = __float2half_rn(rh(v));
    }
}

// ---- HMMA QKV GEMM -> fp16 hi/lo Q,K rowmajor; V transposed ----
__global__ __launch_bounds__(256) void hmma_qkv(const float* __restrict__ bqkv) {
    __shared__ SmemT s;
    int tid = threadIdx.x, wid = tid >> 5, lane = tid & 31;
    int wm = wid >> 2, wn = wid & 3, g = lane >> 2, tg = lane & 3;
    int m0 = blockIdx.y * 128, n0 = blockIdx.x * 128;
    float acc[4][4][4] = {};
    for (int k0 = 0; k0 < DMODEL; k0 += 32) {
        load_tile(g_Xh + (size_t)m0 * DMODEL + k0, DMODEL, s.A0, 128, tid);
        load_tile(g_Xl + (size_t)m0 * DMODEL + k0, DMODEL, s.A1, 128, tid);
        load_tile(g_WqTh + (size_t)n0 * DMODEL + k0, DMODEL, s.B0, 128, tid);
        load_tile(g_WqTl + (size_t)n0 * DMODEL + k0, DMODEL, s.B1, 128, tid);
        __syncthreads();
        warp_mma<4>(s.A0, s.B0, acc, wm, wn, lane);
        warp_mma<4>(s.A0, s.B1, acc, wm, wn, lane);
        warp_mma<4>(s.A1, s.B0, acc, wm, wn, lane);
        __syncthreads();
    }
#pragma unroll
    for (int mi = 0; mi < 4; mi++)
#pragma unroll
        for (int ni = 0; ni < 4; ni++)
#pragma unroll
            for (int rs = 0; rs < 2; rs++) {
                int row = m0 + wm * 64 + mi * 16 + g + rs * 8;
                int col = n0 + wn * 32 + ni * 8 + 2 * tg;
                float v0 = acc[mi][ni][rs * 2] * WISCALE + bqkv[col];
                float v1 = acc[mi][ni][rs * 2 + 1] * WISCALE + bqkv[col + 1];
                int which = col >> 10, hh = (col >> 6) & 15, d = col & 63;
                if (which == 2) {
                    size_t b = (size_t)hh * HDIM * NSEQ;
                    g_VTh[b + (size_t)d * NSEQ + row] = __float2half_rn(v0);
                    g_VTh[b + (size_t)(d + 1) * NSEQ + row] = __float2half_rn(v1);
                    g_VTl[b + (size_t)d * NSEQ + row] = __float2half_rn(rh(v0));
                    g_VTl[b + (size_t)(d + 1) * NSEQ + row] = __float2half_rn(rh(v1));
                } else {
                    __half* dh = (which == 0) ? g_Qh16 : g_Kh16;
                    __half* dl = (which == 0) ? g_Ql16 : g_Kl16;
                    size_t off = ((size_t)hh * NSEQ + row) * HDIM + d;
                    *(__half2*)(dh + off) = __floats2half2_rn(v0, v1);
                    *(__half2*)(dl + off) = __floats2half2_rn(rh(v0), rh(v1));
                }
            }
}

// ---- point projections ----
__global__ void point_proj_kernel(const float* __restrict__ x, const float* __restrict__ Wpq,
                                  const float* __restrict__ bpq, const float* __restrict__ Wpk,
                                  const float* __restrict__ bpk) {
    __shared__ float xs[DMODEL];
    __shared__ float outs[96];
    const int n = blockIdx.x;
    for (int i = threadIdx.x; i < DMODEL; i += blockDim.x) xs[i] = x[(size_t)n * DMODEL + i];
    __syncthreads();
    const int t = threadIdx.x;
    if (t < 96) {
        const bool isq = t < 48;
        const int c = isq ? t : t - 48;
        const float* W = isq ? Wpq : Wpk;
        float s = isq ? bpq[c] : bpk[c];
#pragma unroll 8
        for (int k = 0; k < DMODEL; k++) s = fmaf(xs[k], W[k * 48 + c], s);
        outs[t] = s;
        (isq ? g_pq : g_pk)[((size_t)(c / 3) * NSEQ + n) * 3 + c % 3] = s;
    }
    __syncthreads();
    if (t < 32) {
        int h = t & 15;
        const float* s = (t < 16) ? outs : outs + 48;
        float a = s[h * 3], b = s[h * 3 + 1], cc = s[h * 3 + 2];
        ((t < 16) ? g_sqq : g_sqk)[(size_t)h * NSEQ + n] = a * a + b * b + cc * cc;
    }
}

// ---- flash attention with HMMA matmuls ----
// half smem (in halves): QH 0, QL 10240, KH 20480, KL 30720, PS 40960, VTH 61440, VTL 71680
// float region at half offset 81920
#define FL_SMEM (163840 + 9216)
__global__ __launch_bounds__(256) void flash_hmma(const unsigned char* __restrict__ mask) {
    extern __shared__ __half hsm[];
    __half* QH = hsm;
    __half* QL = hsm + 10240;
    __half* KH = hsm + 20480;
    __half* KL = hsm + 30720;
    __half* PS = hsm + 40960;
    __half* VTH = hsm + 61440;
    __half* VTL = hsm + 71680;
    float* fsm = (float*)(hsm + 81920);
    float* qp = fsm;
    float* kp = fsm + 512;
    float* kms = fsm + 1024;
    float* red = fsm + 1152;
    float* s_m = fsm + 1664;
    float* s_l = fsm + 1792;
    float* s_mn = fsm + 1920;
    float* s_al = fsm + 2048;
    float* s_li = fsm + 2176;

    const int h = blockIdx.y, q0 = blockIdx.x * 128;
    const int tid = threadIdx.x, wid = tid >> 5, lane = tid & 31;
    const int wm = wid >> 2, wn = wid & 3, g = lane >> 2, tg = lane & 3;

    for (int c = 0; c < 2; c++) {
        load_tile(g_Qh16 + ((size_t)(h * NSEQ + q0)) * HDIM + c * 32, HDIM, QH + c * 5120, 128, tid);
        load_tile(g_Ql16 + ((size_t)(h * NSEQ + q0)) * HDIM + c * 32, HDIM, QL + c * 5120, 128, tid);
    }
    if (tid < 128) {
        int n = q0 + tid;
        const float* p = g_pq + ((size_t)h * NSEQ + n) * 3;
        qp[tid * 4] = p[0];
        qp[tid * 4 + 1] = p[1];
        qp[tid * 4 + 2] = p[2];
        qp[tid * 4 + 3] = g_sqq[(size_t)h * NSEQ + n];
        s_m[tid] = -INFINITY;
        s_l[tid] = 0.f;
    }

    float acc_o[4][2][4] = {};

    for (int m0 = 0; m0 < NSEQ; m0 += 128) {
        __syncthreads();
        for (int c = 0; c < 2; c++) {
            load_tile(g_Kh16 + ((size_t)(h * NSEQ + m0)) * HDIM + c * 32, HDIM, KH + c * 5120, 128, tid);
            load_tile(g_Kl16 + ((size_t)(h * NSEQ + m0)) * HDIM + c * 32, HDIM, KL + c * 5120, 128, tid);
        }
        for (int c = 0; c < 4; c++) {
            load_tile(g_VTh + (size_t)h * HDIM * NSEQ + m0 + c * 32, NSEQ, VTH + c * 2560, 64, tid);
            load_tile(g_VTl + (size_t)h * HDIM * NSEQ + m0 + c * 32, NSEQ, VTL + c * 2560, 64, tid);
        }
        if (tid < 128) {
            int m = m0 + tid;
            const float* p = g_pk + ((size_t)h * NSEQ + m) * 3;
            kp[tid * 4] = p[0];
            kp[tid * 4 + 1] = p[1];
            kp[tid * 4 + 2] = p[2];
            kp[tid * 4 + 3] = g_sqk[(size_t)h * NSEQ + m];
            kms[tid] = mask[m] ? 1.f : 0.f;
        }
        __syncthreads();

        float acc_s[4][4][4] = {};
        for (int c = 0; c < 2; c++) {
            warp_mma<4>(QH + c * 5120, KH + c * 5120, acc_s, wm, wn, lane);
            warp_mma<4>(QH + c * 5120, KL + c * 5120, acc_s, wm, wn, lane);
            warp_mma<4>(QL + c * 5120, KH + c * 5120, acc_s, wm, wn, lane);
        }

        // point epilogue + rowmax in fragment layout
#pragma unroll
        for (int mi = 0; mi < 4; mi++)
#pragma unroll
            for (int rs = 0; rs < 2; rs++) {
                int rl = wm * 64 + mi * 16 + g + rs * 8;
                float4 q4 = *(float4*)(qp + rl * 4);
                float rmax = -INFINITY;
#pragma unroll
                for (int ni = 0; ni < 4; ni++) {
                    int cl = wn * 32 + ni * 8 + 2 * tg;
                    float4 k0v = *(float4*)(kp + cl * 4);
                    float4 k1v = *(float4*)(kp + cl * 4 + 4);
                    float s0 = fmaf(0.125f, acc_s[mi][ni][rs * 2],
                                    q4.w + k0v.w - 2.f * (q4.x * k0v.x + q4.y * k0v.y + q4.z * k0v.z));
                    float s1 = fmaf(0.125f, acc_s[mi][ni][rs * 2 + 1],
                                    q4.w + k1v.w - 2.f * (q4.x * k1v.x + q4.y * k1v.y + q4.z * k1v.z));
                    if (kms[cl] != 0.f) s0 = -INFINITY;
                    if (kms[cl + 1] != 0.f) s1 = -INFINITY;
                    acc_s[mi][ni][rs * 2] = s0;
                    acc_s[mi][ni][rs * 2 + 1] = s1;
                    rmax = fmaxf(rmax, fmaxf(s0, s1));
                }
                rmax = fmaxf(rmax, __shfl_xor_sync(~0u, rmax, 1));
                rmax = fmaxf(rmax, __shfl_xor_sync(~0u, rmax, 2));
                if (tg == 0) red[rl * 4 + wn] = rmax;
            }
        __syncthreads();
        if (tid < 128) {
            float mo = s_m[tid];
            float mn = fmaxf(mo, fmaxf(fmaxf(red[tid * 4], red[tid * 4 + 1]),
                                       fmaxf(red[tid * 4 + 2], red[tid * 4 + 3])));
            s_mn[tid] = mn;
            s_al[tid] = (mo == -INFINITY) ? 0.f : __expf(mo - mn);
            s_m[tid] = mn;
        }
        __syncthreads();
        // P (fp16 to smem), logits to g_W, rowsum
#pragma unroll
        for (int mi = 0; mi < 4; mi++)
#pragma unroll
            for (int rs = 0; rs < 2; rs++) {
                int rl = wm * 64 + mi * 16 + g + rs * 8;
                float mn = s_mn[rl];
                float* Wr = g_W + ((size_t)h * NSEQ + q0 + rl) * NSEQ + m0;
                float rsum = 0.f;
#pragma unroll
                for (int ni = 0; ni < 4; ni++) {
                    int cl = wn * 32 + ni * 8 + 2 * tg;
                    float s0 = acc_s[mi][ni][rs * 2], s1 = acc_s[mi][ni][rs * 2 + 1];
                    *(float2*)(Wr + cl) = make_float2(s0, s1);
                    float p0 = (mn == -INFINITY) ? 0.f : __expf(s0 - mn);
                    float p1 = (mn == -INFINITY) ? 0.f : __expf(s1 - mn);
                    *(__half2*)(PS + wn * 5120 + rl * LDS + ni * 8 + 2 * tg) =
                        __floats2half2_rn(p0, p1);
                    rsum += p0 + p1;
                }
                rsum += __shfl_xor_sync(~0u, rsum, 1);
                rsum += __shfl_xor_sync(~0u, rsum, 2);
                if (tg == 0) red[rl * 4 + wn] = rsum;
            }
        __syncthreads();
        if (tid < 128) {
            float l = s_l[tid] * s_al[tid];
            l += red[tid * 4] + red[tid * 4 + 1] + red[tid * 4 + 2] + red[tid * 4 + 3];
            s_l[tid] = l;
        }
        // rescale + PV
#pragma unroll
        for (int mi = 0; mi < 4; mi++)
#pragma unroll
            for (int rs = 0; rs < 2; rs++) {
                int rl = wm * 64 + mi * 16 + g + rs * 8;
                float al = s_al[rl];
#pragma unroll
                for (int ni = 0; ni < 2; ni++) {
                    acc_o[mi][ni][rs * 2] *= al;
                    acc_o[mi][ni][rs * 2 + 1] *= al;
                }
            }
        for (int c = 0; c < 4; c++) {
            warp_mma<2>(PS + c * 5120, VTH + c * 2560, acc_o, wm, wn, lane);
            warp_mma<2>(PS + c * 5120, VTL + c * 2560, acc_o, wm, wn, lane);
        }
    }
    __syncthreads();
    if (tid < 128) {
        float l = s_l[tid];
        float li = (l > 0.f) ? 1.f / l : 0.f;
        s_li[tid] = li;
        g_m[(size_t)h * NSEQ + q0 + tid] = s_m[tid];
        g_li[(size_t)h * NSEQ + q0 + tid] = li;
    }
    __syncthreads();
#pragma unroll
    for (int mi = 0; mi < 4; mi++)
#pragma unroll
        for (int rs = 0; rs < 2; rs++) {
            int rl = wm * 64 + mi * 16 + g + rs * 8;
            float li = s_li[rl];
            int row = q0 + rl;
#pragma unroll
            for (int ni = 0; ni < 2; ni++) {
                int d = wn * 16 + ni * 8 + 2 * tg;
                float v0 = acc_o[mi][ni][rs * 2] * li;
                float v1 = acc_o[mi][ni][rs * 2 + 1] * li;
                size_t off = (size_t)row * DMODEL + h * HDIM + d;
                *(__half2*)(g_Ath + off) = __floats2half2_rn(v0, v1);
                *(__half2*)(g_Atl + off) = __floats2half2_rn(rh(v0), rh(v1));
            }
        }
}

// ---- meanw from fp32 logits ----
__global__ void meanw_kernel(float* __restrict__ mw) {
    size_t base = ((size_t)blockIdx.x * 256 + threadIdx.x) * 4;
    int n = (int)(base >> 11);
    float a0 = 0.f, a1 = 0.f, a2 = 0.f, a3 = 0.f;
#pragma unroll
    for (int h = 0; h < NHEADS; h++) {
        float m = g_m[(size_t)h * NSEQ + n];
        float li = g_li[(size_t)h * NSEQ + n];
        float4 s4 = *(const float4*)(g_W + (size_t)h * NN + base);
        if (li > 0.f) {
            a0 += __expf(s4.x - m) * li;
            a1 += __expf(s4.y - m) * li;
            a2 += __expf(s4.z - m) * li;
            a3 += __expf(s4.w - m) * li;
        }
    }
    const float iv = 1.f / NHEADS;
    *(float4*)(mw + base) = make_float4(a0 * iv, a1 * iv, a2 * iv, a3 * iv);
}

// ---- HMMA out-proj + bias + residual ----
__global__ __launch_bounds__(256) void hmma_out(const float* __restrict__ bo,
                                                const float* __restrict__ x) {
    __shared__ SmemT s;
    int tid = threadIdx.x, wid = tid >> 5, lane = tid & 31;
    int wm = wid >> 2, wn = wid & 3, g = lane >> 2, tg = lane & 3;
    int m0 = blockIdx.y * 128, n0 = blockIdx.x * 128;
    float acc[4][4][4] = {};
    for (int k0 = 0; k0 < DMODEL; k0 += 32) {
        load_tile(g_Ath + (size_t)m0 * DMODEL + k0, DMODEL, s.A0, 128, tid);
        load_tile(g_Atl + (size_t)m0 * DMODEL + k0, DMODEL, s.A1, 128, tid);
        load_tile(g_WoTh + (size_t)n0 * DMODEL + k0, DMODEL, s.B0, 128, tid);
        load_tile(g_WoTl + (size_t)n0 * DMODEL + k0, DMODEL, s.B1, 128, tid);
        __syncthreads();
        warp_mma<4>(s.A0, s.B0, acc, wm, wn, lane);
        warp_mma<4>(s.A0, s.B1, acc, wm, wn, lane);
        warp_mma<4>(s.A1, s.B0, acc, wm, wn, lane);
        __syncthreads();
    }
#pragma unroll
    for (int mi = 0; mi < 4; mi++)
#pragma unroll
        for (int ni = 0; ni < 4; ni++)
#pragma unroll
            for (int rs = 0; rs < 2; rs++) {
                int row = m0 + wm * 64 + mi * 16 + g + rs * 8;
                int col = n0 + wn * 32 + ni * 8 + 2 * tg;
                size_t off = (size_t)row * DMODEL + col;
                g_res[off] = acc[mi][ni][rs * 2] * WISCALE + bo[col] + x[off];
                g_res[off + 1] = acc[mi][ni][rs * 2 + 1] * WISCALE + bo[col + 1] + x[off + 1];
            }
}

__global__ void ln_kernel(const float* __restrict__ gamma, const float* __restrict__ beta,
                          float* __restrict__ out) {
    const int n = blockIdx.x, tid = threadIdx.x;
    __shared__ float sr[256];
    __shared__ float s_mu, s_rs;
    const float* r = g_res + (size_t)n * DMODEL;
    float v[4], s = 0.f;
#pragma unroll
    for (int k = 0; k < 4; k++) {
        v[k] = r[tid + k * 256];
        s += v[k];
    }
    sr[tid] = s;
    __syncthreads();
    for (int o = 128; o; o >>= 1) {
        if (tid < o) sr[tid] += sr[tid + o];
        __syncthreads();
    }
    if (tid == 0) s_mu = sr[0] * (1.f / DMODEL);
    __syncthreads();
    float mu = s_mu, s2 = 0.f;
#pragma unroll
    for (int k = 0; k < 4; k++) {
        float d = v[k] - mu;
        s2 += d * d;
    }
    sr[tid] = s2;
    __syncthreads();
    for (int o = 128; o; o >>= 1) {
        if (tid < o) sr[tid] += sr[tid + o];
        __syncthreads();
    }
    if (tid == 0) s_rs = rsqrtf(sr[0] * (1.f / DMODEL) + 1e-5f);
    __syncthreads();
    float rs = s_rs;
#pragma unroll
    for (int k = 0; k < 4; k++) {
        int c = tid + k * 256;
        out[(size_t)n * DMODEL + c] = (v[k] - mu) * rs * gamma[c] + beta[c];
    }
}

extern "C" void kernel_launch(void* const* d_in, const int* in_sizes, int n_in, void* d_out,
                              int out_size) {
    const float* x = (const float*)d_in[0];
    const unsigned char* mask = (const unsigned char*)d_in[2];
    const float* Wqkv = (const float*)d_in[3];
    const float* bqkv = (const float*)d_in[4];
    const float* Wpq = (const float*)d_in[5];
    const float* bpq = (const float*)d_in[6];
    const float* Wpk = (const float*)d_in[7];
    const float* bpk = (const float*)d_in[8];
    const float* Wo = (const float*)d_in[9];
    const float* bo = (const float*)d_in[10];
    const float* gamma = (const float*)d_in[11];
    const float* beta = (const float*)d_in[12];
    float* out = (float*)d_out;
    float* meanw = out + (size_t)NSEQ * DMODEL;

    cudaFuncSetAttribute(flash_hmma, cudaFuncAttributeMaxDynamicSharedMemorySize, FL_SMEM);

    split_x<<<NSEQ * DMODEL / 256, 256>>>(x);
    tsplit_wq<<<dim3(D3 / 32, DMODEL / 32), dim3(32, 8)>>>(Wqkv);
    tsplit_wo<<<dim3(DMODEL / 32, DMODEL / 32), dim3(32, 8)>>>(Wo);
    hmma_qkv<<<dim3(D3 / 128, NSEQ / 128), 256>>>(bqkv);
    point_proj_kernel<<<NSEQ, 128>>>(x, Wpq, bpq, Wpk, bpk);
    flash_hmma<<<dim3(NSEQ / 128, NHEADS), 256, FL_SMEM>>>(mask);
    meanw_kernel<<<NN / 1024, 256>>>(meanw);
    hmma_out<<<dim3(DMODEL / 128, NSEQ / 128), 256>>>(bo, x);
    ln_kernel<<<NSEQ, 256>>>(gamma, beta, out);
}